// round 7
// baseline (speedup 1.0000x reference)
#include <cuda_runtime.h>
#include <math.h>

#define FULL 0xFFFFFFFFu
typedef unsigned long long u64;

// ---- packed f32x2 helpers (sm_103a) ------------------------------------
__device__ __forceinline__ u64 pk2(float lo, float hi) {
    u64 r; asm("mov.b64 %0, {%1, %2};" : "=l"(r) : "f"(lo), "f"(hi)); return r;
}
__device__ __forceinline__ float lo2(u64 x) { return __uint_as_float((unsigned)x); }
__device__ __forceinline__ float hi2(u64 x) { return __uint_as_float((unsigned)(x >> 32)); }
__device__ __forceinline__ u64 fma2(u64 a, u64 b, u64 c) {
    u64 d; asm("fma.rn.f32x2 %0, %1, %2, %3;" : "=l"(d) : "l"(a), "l"(b), "l"(c)); return d;
}
__device__ __forceinline__ u64 mul2(u64 a, u64 b) {
    u64 d; asm("mul.rn.f32x2 %0, %1, %2;" : "=l"(d) : "l"(a), "l"(b)); return d;
}
__device__ __forceinline__ u64 add2(u64 a, u64 b) {
    u64 d; asm("add.rn.f32x2 %0, %1, %2;" : "=l"(d) : "l"(a), "l"(b)); return d;
}
__device__ __forceinline__ u64 shfl64(u64 x, int src) {
    unsigned lo = (unsigned)x, hi = (unsigned)(x >> 32);
    lo = __shfl_sync(FULL, lo, src);
    hi = __shfl_sync(FULL, hi, src);
    return ((u64)hi << 32) | (u64)lo;
}
__device__ __forceinline__ u64 shfl64x(u64 x, int mask) {
    unsigned lo = (unsigned)x, hi = (unsigned)(x >> 32);
    lo = __shfl_xor_sync(FULL, lo, mask);
    hi = __shfl_xor_sync(FULL, hi, mask);
    return ((u64)hi << 32) | (u64)lo;
}
__device__ __forceinline__ float red2(u64 a, u64 b, u64 c, u64 d) {
    u64 s = add2(add2(a, b), add2(c, d));
    return lo2(s) + hi2(s);
}

// One warp per 64x64 SPD matrix. Lane k holds two columns (u, v) packed as
// 32 x f32x2. One-sided Jacobi, recursive-halving tournament, fused
// next-pairing dot. One-division angle: t = b/(a+copysign(D,a)),
// D = sqrt(a^2+b^2). Sweeps 0-5 run ballot-free (never converged there);
// sweeps 6+ add the ballot-gated skip path + sweep early exit.
// Cap 16 sweeps (10 measured insufficient: rel_err 0.099).
__global__ __launch_bounds__(32, 13) void logeig_jacobi(const float* __restrict__ P,
                                                        float* __restrict__ X,
                                                        int nmat) {
    const int m = blockIdx.x;
    if (m >= nmat) return;
    const int k = threadIdx.x;
    const float* __restrict__ Pm = P + (size_t)m * 4096;
    float* __restrict__ Xm = X + (size_t)m * 4096;

    u64 U[32], V[32];
#pragma unroll
    for (int j = 0; j < 32; ++j) {
        U[j] = pk2(Pm[(2 * j) * 64 + k],        Pm[(2 * j + 1) * 64 + k]);
        V[j] = pk2(Pm[(2 * j) * 64 + (k + 32)], Pm[(2 * j + 1) * 64 + (k + 32)]);
    }

    float du = 0.f, dv = 0.f;

    for (int sweep = 0; sweep < 16; ++sweep) {
        const bool gated = (sweep >= 6);   // ballot/skip machinery only late

        // exact norms at sweep start
        {
            u64 a0 = 0, a1 = 0, b0 = 0, b1 = 0;
#pragma unroll
            for (int j = 0; j < 32; j += 2) {
                a0 = fma2(U[j], U[j], a0);     a1 = fma2(U[j + 1], U[j + 1], a1);
                b0 = fma2(V[j], V[j], b0);     b1 = fma2(V[j + 1], V[j + 1], b1);
            }
            u64 a = add2(a0, a1), b = add2(b0, b1);
            du = lo2(a) + hi2(a);
            dv = lo2(b) + hi2(b);
        }

        unsigned any = 0u;
        for (int g = 32; g >= 1; g >>= 1) {
            const int src = (k & ~(g - 1)) | ((k + 1) & (g - 1));

            // fresh dot at level start
            float x;
            {
                u64 x0 = 0, x1 = 0, x2 = 0, x3 = 0;
#pragma unroll
                for (int j = 0; j < 32; j += 4) {
                    x0 = fma2(U[j],     V[j],     x0);
                    x1 = fma2(U[j + 1], V[j + 1], x1);
                    x2 = fma2(U[j + 2], V[j + 2], x2);
                    x3 = fma2(U[j + 3], V[j + 3], x3);
                }
                x = red2(x0, x1, x2, x3);
            }

            for (int r = 0; r < g; ++r) {
                bool rot = (x * x > 1e-8f * du * dv);
                unsigned bal;
                if (gated) {
                    bal = __ballot_sync(FULL, rot);
                    any |= bal;
                } else {
                    bal = FULL;
                }

                u64 x0 = 0, x1 = 0, x2 = 0, x3 = 0;
                if (bal) {
                    // full path: one-division angle, rotate, fused next dot
                    float a = dv - du;
                    float b = 2.0f * x;
                    float D = sqrtf(fmaf(a, a, b * b));
                    float t = __fdividef(b, a + copysignf(D, a));
                    if (!rot) t = 0.0f;                   // c=1, s=0 fallthrough
                    float c = rsqrtf(fmaf(t, t, 1.0f));
                    float s = t * c;

                    float ndu = fmaf(-t, x, du);
                    float ndv = fmaf( t, x, dv);

                    u64 cc = pk2(c, c), ss = pk2(s, s), ns = pk2(-s, -s);
#pragma unroll
                    for (int j = 0; j < 32; ++j) {
                        u64 un = fma2(cc, U[j], mul2(ns, V[j]));
                        u64 vn = fma2(cc, V[j], mul2(ss, U[j]));
                        U[j] = un;
                        V[j] = shfl64(vn, src);
                        if ((j & 3) == 0)      x0 = fma2(un, V[j], x0);
                        else if ((j & 3) == 1) x1 = fma2(un, V[j], x1);
                        else if ((j & 3) == 2) x2 = fma2(un, V[j], x2);
                        else                   x3 = fma2(un, V[j], x3);
                    }
                    du = ndu;
                    dv = __shfl_sync(FULL, ndv, src);
                } else {
                    // skip path: no lane rotates -> advance pairing + dot only
#pragma unroll
                    for (int j = 0; j < 32; ++j) {
                        V[j] = shfl64(V[j], src);
                        if ((j & 3) == 0)      x0 = fma2(U[j], V[j], x0);
                        else if ((j & 3) == 1) x1 = fma2(U[j], V[j], x1);
                        else if ((j & 3) == 2) x2 = fma2(U[j], V[j], x2);
                        else                   x3 = fma2(U[j], V[j], x3);
                    }
                    dv = __shfl_sync(FULL, dv, src);
                }
                x = red2(x0, x1, x2, x3);
            }

            // split: lower half-lanes keep u-set, upper keep v-set
            if (g > 1) {
                const int h = g >> 1;
                const bool low = (k & h) == 0;
#pragma unroll
                for (int j = 0; j < 32; ++j) {
                    u64 pu = shfl64x(U[j], h);
                    u64 pv = shfl64x(V[j], h);
                    if (low) V[j] = pu; else U[j] = pv;
                }
                float pdu = __shfl_xor_sync(FULL, du, h);
                float pdv = __shfl_xor_sync(FULL, dv, h);
                if (low) dv = pdu; else du = pdv;
            }
        }
        if (gated && any == 0u) break;
    }

    // exact final norms -> log weights  g_p = 0.5*log(d_p)/d_p
    float fdu, fdv;
    {
        u64 a0 = 0, a1 = 0, b0 = 0, b1 = 0;
#pragma unroll
        for (int j = 0; j < 32; j += 2) {
            a0 = fma2(U[j], U[j], a0);     a1 = fma2(U[j + 1], U[j + 1], a1);
            b0 = fma2(V[j], V[j], b0);     b1 = fma2(V[j + 1], V[j + 1], b1);
        }
        u64 a = add2(a0, a1), b = add2(b0, b1);
        fdu = lo2(a) + hi2(a);
        fdv = lo2(b) + hi2(b);
    }

    __shared__ __align__(16) float W[64][66];
    __shared__ float gw[64];
#pragma unroll
    for (int j = 0; j < 32; ++j) {
        W[k][2 * j]          = lo2(U[j]);
        W[k][2 * j + 1]      = hi2(U[j]);
        W[k + 32][2 * j]     = lo2(V[j]);
        W[k + 32][2 * j + 1] = hi2(V[j]);
    }
    gw[k]      = 0.5f * __logf(fdu) / fdu;
    gw[k + 32] = 0.5f * __logf(fdv) / fdv;
    __syncwarp();

    // X = sum_p g_p w_p w_p^T ; lane k emits columns k and k+32, in
    // 16-wide row quarters to keep peak register pressure under the cap.
#pragma unroll
    for (int half = 0; half < 2; ++half) {
        const int col = k + 32 * half;
#pragma unroll
        for (int q = 0; q < 2; ++q) {
            u64 acc[16];
#pragma unroll
            for (int j = 0; j < 16; ++j) acc[j] = 0ull;
            for (int p = 0; p < 64; ++p) {
                float sp = gw[p] * W[p][col];
                u64 sp2 = pk2(sp, sp);
                const u64* row = (const u64*)&W[p][0] + 16 * q;
#pragma unroll
                for (int j = 0; j < 16; ++j) acc[j] = fma2(sp2, row[j], acc[j]);
            }
#pragma unroll
            for (int j = 0; j < 16; ++j) {
                Xm[(32 * q + 2 * j) * 64 + col]     = lo2(acc[j]);
                Xm[(32 * q + 2 * j + 1) * 64 + col] = hi2(acc[j]);
            }
        }
    }
}

extern "C" void kernel_launch(void* const* d_in, const int* in_sizes, int n_in,
                              void* d_out, int out_size) {
    const float* P = (const float*)d_in[0];
    float* X = (float*)d_out;
    int nmat = in_sizes[0] / 4096;
    logeig_jacobi<<<nmat, 32>>>(P, X, nmat);
}

// round 8
// speedup vs baseline: 4.0529x; 4.0529x over previous
#include <cuda_runtime.h>
#include <math.h>

#define FULL 0xFFFFFFFFu
typedef unsigned long long u64;

// ---- packed f32x2 helpers (sm_103a) ------------------------------------
__device__ __forceinline__ u64 pk2(float lo, float hi) {
    u64 r; asm("mov.b64 %0, {%1, %2};" : "=l"(r) : "f"(lo), "f"(hi)); return r;
}
__device__ __forceinline__ float lo2(u64 x) { return __uint_as_float((unsigned)x); }
__device__ __forceinline__ float hi2(u64 x) { return __uint_as_float((unsigned)(x >> 32)); }
__device__ __forceinline__ u64 fma2(u64 a, u64 b, u64 c) {
    u64 d; asm("fma.rn.f32x2 %0, %1, %2, %3;" : "=l"(d) : "l"(a), "l"(b), "l"(c)); return d;
}
__device__ __forceinline__ u64 mul2(u64 a, u64 b) {
    u64 d; asm("mul.rn.f32x2 %0, %1, %2;" : "=l"(d) : "l"(a), "l"(b)); return d;
}
__device__ __forceinline__ u64 add2(u64 a, u64 b) {
    u64 d; asm("add.rn.f32x2 %0, %1, %2;" : "=l"(d) : "l"(a), "l"(b)); return d;
}
__device__ __forceinline__ u64 shfl64(u64 x, int src) {
    unsigned lo = (unsigned)x, hi = (unsigned)(x >> 32);
    lo = __shfl_sync(FULL, lo, src);
    hi = __shfl_sync(FULL, hi, src);
    return ((u64)hi << 32) | (u64)lo;
}
__device__ __forceinline__ u64 shfl64x(u64 x, int mask) {
    unsigned lo = (unsigned)x, hi = (unsigned)(x >> 32);
    lo = __shfl_xor_sync(FULL, lo, mask);
    hi = __shfl_xor_sync(FULL, hi, mask);
    return ((u64)hi << 32) | (u64)lo;
}
__device__ __forceinline__ float red2(u64 a, u64 b, u64 c, u64 d) {
    u64 s = add2(add2(a, b), add2(c, d));
    return lo2(s) + hi2(s);
}

// One warp per 64x64 SPD matrix. Lane k holds two columns (u, v) packed as
// 32 x f32x2. One-sided Jacobi, recursive-halving tournament, fused
// next-pairing dot. One-division angle: t = b/(a+copysign(D,a)),
// D = sqrt(a^2+b^2). Sweeps 0-5 run ballot-free (never converged there);
// sweeps 6+ add the ballot-gated skip path + sweep early exit.
// Cap 16 sweeps (10 measured insufficient: rel_err 0.099).
// __launch_bounds__(32, 12): 170-reg cap = 3 warps/SMSP without spills.
// (32, 13) measured CATASTROPHIC: ptxas drops to 128 regs and spills U/V
// to local memory -> 4x slowdown, L2 55%. Do not raise past 12.
__global__ __launch_bounds__(32, 12) void logeig_jacobi(const float* __restrict__ P,
                                                        float* __restrict__ X,
                                                        int nmat) {
    const int m = blockIdx.x;
    if (m >= nmat) return;
    const int k = threadIdx.x;
    const float* __restrict__ Pm = P + (size_t)m * 4096;
    float* __restrict__ Xm = X + (size_t)m * 4096;

    u64 U[32], V[32];
#pragma unroll
    for (int j = 0; j < 32; ++j) {
        U[j] = pk2(Pm[(2 * j) * 64 + k],        Pm[(2 * j + 1) * 64 + k]);
        V[j] = pk2(Pm[(2 * j) * 64 + (k + 32)], Pm[(2 * j + 1) * 64 + (k + 32)]);
    }

    float du = 0.f, dv = 0.f;

    for (int sweep = 0; sweep < 16; ++sweep) {
        const bool gated = (sweep >= 6);   // ballot/skip machinery only late

        // exact norms at sweep start
        {
            u64 a0 = 0, a1 = 0, b0 = 0, b1 = 0;
#pragma unroll
            for (int j = 0; j < 32; j += 2) {
                a0 = fma2(U[j], U[j], a0);     a1 = fma2(U[j + 1], U[j + 1], a1);
                b0 = fma2(V[j], V[j], b0);     b1 = fma2(V[j + 1], V[j + 1], b1);
            }
            u64 a = add2(a0, a1), b = add2(b0, b1);
            du = lo2(a) + hi2(a);
            dv = lo2(b) + hi2(b);
        }

        unsigned any = 0u;
        for (int g = 32; g >= 1; g >>= 1) {
            const int src = (k & ~(g - 1)) | ((k + 1) & (g - 1));

            // fresh dot at level start
            float x;
            {
                u64 x0 = 0, x1 = 0, x2 = 0, x3 = 0;
#pragma unroll
                for (int j = 0; j < 32; j += 4) {
                    x0 = fma2(U[j],     V[j],     x0);
                    x1 = fma2(U[j + 1], V[j + 1], x1);
                    x2 = fma2(U[j + 2], V[j + 2], x2);
                    x3 = fma2(U[j + 3], V[j + 3], x3);
                }
                x = red2(x0, x1, x2, x3);
            }

            for (int r = 0; r < g; ++r) {
                bool rot = (x * x > 1e-8f * du * dv);
                unsigned bal;
                if (gated) {
                    bal = __ballot_sync(FULL, rot);
                    any |= bal;
                } else {
                    bal = FULL;
                }

                u64 x0 = 0, x1 = 0, x2 = 0, x3 = 0;
                if (bal) {
                    // full path: one-division angle, rotate, fused next dot
                    float a = dv - du;
                    float b = 2.0f * x;
                    float D = sqrtf(fmaf(a, a, b * b));
                    float t = __fdividef(b, a + copysignf(D, a));
                    if (!rot) t = 0.0f;                   // c=1, s=0 fallthrough
                    float c = rsqrtf(fmaf(t, t, 1.0f));
                    float s = t * c;

                    float ndu = fmaf(-t, x, du);
                    float ndv = fmaf( t, x, dv);

                    u64 cc = pk2(c, c), ss = pk2(s, s), ns = pk2(-s, -s);
#pragma unroll
                    for (int j = 0; j < 32; ++j) {
                        u64 un = fma2(cc, U[j], mul2(ns, V[j]));
                        u64 vn = fma2(cc, V[j], mul2(ss, U[j]));
                        U[j] = un;
                        V[j] = shfl64(vn, src);
                        if ((j & 3) == 0)      x0 = fma2(un, V[j], x0);
                        else if ((j & 3) == 1) x1 = fma2(un, V[j], x1);
                        else if ((j & 3) == 2) x2 = fma2(un, V[j], x2);
                        else                   x3 = fma2(un, V[j], x3);
                    }
                    du = ndu;
                    dv = __shfl_sync(FULL, ndv, src);
                } else {
                    // skip path: no lane rotates -> advance pairing + dot only
#pragma unroll
                    for (int j = 0; j < 32; ++j) {
                        V[j] = shfl64(V[j], src);
                        if ((j & 3) == 0)      x0 = fma2(U[j], V[j], x0);
                        else if ((j & 3) == 1) x1 = fma2(U[j], V[j], x1);
                        else if ((j & 3) == 2) x2 = fma2(U[j], V[j], x2);
                        else                   x3 = fma2(U[j], V[j], x3);
                    }
                    dv = __shfl_sync(FULL, dv, src);
                }
                x = red2(x0, x1, x2, x3);
            }

            // split: lower half-lanes keep u-set, upper keep v-set
            if (g > 1) {
                const int h = g >> 1;
                const bool low = (k & h) == 0;
#pragma unroll
                for (int j = 0; j < 32; ++j) {
                    u64 pu = shfl64x(U[j], h);
                    u64 pv = shfl64x(V[j], h);
                    if (low) V[j] = pu; else U[j] = pv;
                }
                float pdu = __shfl_xor_sync(FULL, du, h);
                float pdv = __shfl_xor_sync(FULL, dv, h);
                if (low) dv = pdu; else du = pdv;
            }
        }
        if (gated && any == 0u) break;
    }

    // exact final norms -> log weights  g_p = 0.5*log(d_p)/d_p
    float fdu, fdv;
    {
        u64 a0 = 0, a1 = 0, b0 = 0, b1 = 0;
#pragma unroll
        for (int j = 0; j < 32; j += 2) {
            a0 = fma2(U[j], U[j], a0);     a1 = fma2(U[j + 1], U[j + 1], a1);
            b0 = fma2(V[j], V[j], b0);     b1 = fma2(V[j + 1], V[j + 1], b1);
        }
        u64 a = add2(a0, a1), b = add2(b0, b1);
        fdu = lo2(a) + hi2(a);
        fdv = lo2(b) + hi2(b);
    }

    __shared__ __align__(16) float W[64][66];
    __shared__ float gw[64];
#pragma unroll
    for (int j = 0; j < 32; ++j) {
        W[k][2 * j]          = lo2(U[j]);
        W[k][2 * j + 1]      = hi2(U[j]);
        W[k + 32][2 * j]     = lo2(V[j]);
        W[k + 32][2 * j + 1] = hi2(V[j]);
    }
    gw[k]      = 0.5f * __logf(fdu) / fdu;
    gw[k + 32] = 0.5f * __logf(fdv) / fdv;
    __syncwarp();

    // X = sum_p g_p w_p w_p^T ; lane k emits columns k and k+32, in
    // 16-wide row quarters to keep peak register pressure under the cap.
#pragma unroll
    for (int half = 0; half < 2; ++half) {
        const int col = k + 32 * half;
#pragma unroll
        for (int q = 0; q < 2; ++q) {
            u64 acc[16];
#pragma unroll
            for (int j = 0; j < 16; ++j) acc[j] = 0ull;
            for (int p = 0; p < 64; ++p) {
                float sp = gw[p] * W[p][col];
                u64 sp2 = pk2(sp, sp);
                const u64* row = (const u64*)&W[p][0] + 16 * q;
#pragma unroll
                for (int j = 0; j < 16; ++j) acc[j] = fma2(sp2, row[j], acc[j]);
            }
#pragma unroll
            for (int j = 0; j < 16; ++j) {
                Xm[(32 * q + 2 * j) * 64 + col]     = lo2(acc[j]);
                Xm[(32 * q + 2 * j + 1) * 64 + col] = hi2(acc[j]);
            }
        }
    }
}

extern "C" void kernel_launch(void* const* d_in, const int* in_sizes, int n_in,
                              void* d_out, int out_size) {
    const float* P = (const float*)d_in[0];
    float* X = (float*)d_out;
    int nmat = in_sizes[0] / 4096;
    logeig_jacobi<<<nmat, 32>>>(P, X, nmat);
}